// round 4
// baseline (speedup 1.0000x reference)
#include <cuda_runtime.h>

// Problem: ImprovedRNN (LSTM) B=256, T=1024, I=64, H=25, O=64, fp32.
// Inputs (metadata order): x[B,T,I], W_ih[4H,I], W_hh[4H,H], b_ih[4H], b_hh[4H],
//                          W_fc[O,H], b_fc[O].  Output: [B,T,O] fp32.
// Gate order (PyTorch): i, f, g, o  (rows 0..24, 25..49, 50..74, 75..99).

static constexpr int Bb = 256;
static constexpr int Tt = 1024;
static constexpr int Ii = 64;
static constexpr int Hh = 25;
static constexpr int Gg = 4 * Hh;   // 100
static constexpr int Oo = 64;
static constexpr int ROWS = Bb * Tt;          // 262144
static constexpr int THREADS = 128;

// Scratch (device globals: allocation APIs are forbidden).
__device__ float g_gates[(size_t)ROWS * Gg];   // [B*T, 100]  (~100 MB)
__device__ float g_hs[(size_t)ROWS * Hh];      // [B*T, 25]   (~25 MB)

__device__ __forceinline__ float sigmoid_f(float x) {
    return __fdividef(1.0f, 1.0f + __expf(-x));
}
__device__ __forceinline__ float tanh_f(float x) {
    // tanh(x) = 2*sigmoid(2x) - 1  (abs error ~1e-7, fine vs 1e-3 tolerance)
    return 2.0f * __fdividef(1.0f, 1.0f + __expf(-2.0f * x)) - 1.0f;
}

// ---------------------------------------------------------------------------
// Phase 1: gates_x[row][j] = sum_i x[row][i] * W_ih[j][i] + (b_ih[j]+b_hh[j])
// One thread per row; x row in registers (float4 x16); W_ih in shared.
// ---------------------------------------------------------------------------
__global__ __launch_bounds__(THREADS) void gates_kernel(
    const float* __restrict__ x,
    const float* __restrict__ W_ih,
    const float* __restrict__ b_ih,
    const float* __restrict__ b_hh)
{
    __shared__ float Wsh[Gg * Ii];   // 25.6 KB
    __shared__ float bsh[Gg];

    const int tid = threadIdx.x;
    for (int idx = tid; idx < Gg * Ii; idx += THREADS) Wsh[idx] = W_ih[idx];
    if (tid < Gg) bsh[tid] = b_ih[tid] + b_hh[tid];
    __syncthreads();

    const size_t row = (size_t)blockIdx.x * THREADS + tid;

    float4 xr[16];
    const float4* xp = (const float4*)(x + row * Ii);
#pragma unroll
    for (int i = 0; i < 16; ++i) xr[i] = xp[i];

    float* gout = g_gates + row * Gg;

#pragma unroll 1
    for (int j4 = 0; j4 < Gg / 4; ++j4) {
        float acc[4];
#pragma unroll
        for (int jj = 0; jj < 4; ++jj) {
            const int j = 4 * j4 + jj;
            const float4* Wv = (const float4*)(Wsh + j * Ii);
            float s = bsh[j];
#pragma unroll
            for (int i = 0; i < 16; ++i) {
                float4 w = Wv[i];
                s += xr[i].x * w.x;
                s += xr[i].y * w.y;
                s += xr[i].z * w.z;
                s += xr[i].w * w.w;
            }
            acc[jj] = s;
        }
        ((float4*)gout)[j4] = make_float4(acc[0], acc[1], acc[2], acc[3]);
    }
}

// ---------------------------------------------------------------------------
// Phase 2: sequential LSTM recurrence. One CTA per batch element, 128 threads.
// Thread j<100 owns gate j (W_hh row in registers). h lives in shared.
// gates for step t+1 prefetched during step t (they sit in L2).
// ---------------------------------------------------------------------------
__global__ __launch_bounds__(THREADS) void lstm_kernel(
    const float* __restrict__ W_hh)
{
    __shared__ float h_sh[32];
    __shared__ float act_sh[112];

    const int j = threadIdx.x;
    const int b = blockIdx.x;

    float Wrow[Hh];
    if (j < Gg) {
#pragma unroll
        for (int k = 0; k < Hh; ++k) Wrow[k] = W_hh[j * Hh + k];
    }
    if (j < 32) h_sh[j] = 0.0f;

    float c = 0.0f;
    const float* gb = g_gates + (size_t)b * Tt * Gg;
    float*       hb = g_hs    + (size_t)b * Tt * Hh;
    __syncthreads();

    float gin = (j < Gg) ? gb[j] : 0.0f;

    for (int t = 0; t < Tt; ++t) {
        float a = 0.0f;
        if (j < Gg) {
            float acc0 = 0.0f, acc1 = 0.0f;
#pragma unroll
            for (int k = 0; k < Hh - 1; k += 2) {
                acc0 += Wrow[k]     * h_sh[k];
                acc1 += Wrow[k + 1] * h_sh[k + 1];
            }
            acc0 += Wrow[Hh - 1] * h_sh[Hh - 1];
            const float g = gin + acc0 + acc1;
            if (j >= 50 && j < 75) a = tanh_f(g);      // cell gate g
            else                   a = sigmoid_f(g);   // i, f, o
        }
        // prefetch next step's gates early (hide L2 latency behind barrier)
        if (t + 1 < Tt && j < Gg) gin = gb[(size_t)(t + 1) * Gg + j];

        if (j < Gg) act_sh[j] = a;
        __syncthreads();

        if (j < Hh) {
            const float iv = act_sh[j];
            const float fv = act_sh[25 + j];
            const float gv = act_sh[50 + j];
            const float ov = act_sh[75 + j];
            c = fv * c + iv * gv;
            const float h = ov * tanh_f(c);
            h_sh[j] = h;
            hb[(size_t)t * Hh + j] = h;
        }
        __syncthreads();
    }
}

// ---------------------------------------------------------------------------
// Phase 3: out[row][o] = b_fc[o] + sum_k hs[row][k] * W_fc[o][k]
// One thread per row; W_fc transposed into shared (Wt[k][o]) for float4 reads.
// ---------------------------------------------------------------------------
__global__ __launch_bounds__(THREADS) void fc_kernel(
    const float* __restrict__ W_fc,
    const float* __restrict__ b_fc,
    float* __restrict__ out)
{
    __shared__ float Wt[Hh * Oo];   // Wt[k*64 + o] = W_fc[o*25 + k]
    __shared__ float bsh[Oo];

    const int tid = threadIdx.x;
    for (int idx = tid; idx < Hh * Oo; idx += THREADS) {
        const int k = idx / Oo;
        const int o = idx % Oo;
        Wt[idx] = W_fc[o * Hh + k];
    }
    if (tid < Oo) bsh[tid] = b_fc[tid];
    __syncthreads();

    const size_t row = (size_t)blockIdx.x * THREADS + tid;
    const float* hp = g_hs + row * Hh;

    float hv[Hh];
#pragma unroll
    for (int k = 0; k < Hh; ++k) hv[k] = hp[k];

    float acc[Oo];
#pragma unroll
    for (int o = 0; o < Oo; ++o) acc[o] = bsh[o];

#pragma unroll 1
    for (int k = 0; k < Hh; ++k) {
        const float hk = hv[k];
        const float4* wv = (const float4*)(Wt + k * Oo);
#pragma unroll
        for (int o4 = 0; o4 < Oo / 4; ++o4) {
            float4 w = wv[o4];
            acc[4 * o4 + 0] += hk * w.x;
            acc[4 * o4 + 1] += hk * w.y;
            acc[4 * o4 + 2] += hk * w.z;
            acc[4 * o4 + 3] += hk * w.w;
        }
    }

    float4* op = (float4*)(out + row * Oo);
#pragma unroll
    for (int o4 = 0; o4 < Oo / 4; ++o4)
        op[o4] = make_float4(acc[4 * o4 + 0], acc[4 * o4 + 1],
                             acc[4 * o4 + 2], acc[4 * o4 + 3]);
}

// ---------------------------------------------------------------------------
extern "C" void kernel_launch(void* const* d_in, const int* in_sizes, int n_in,
                              void* d_out, int out_size)
{
    const float* x    = (const float*)d_in[0];
    const float* W_ih = (const float*)d_in[1];
    const float* W_hh = (const float*)d_in[2];
    const float* b_ih = (const float*)d_in[3];
    const float* b_hh = (const float*)d_in[4];
    const float* W_fc = (const float*)d_in[5];
    const float* b_fc = (const float*)d_in[6];
    float* out = (float*)d_out;

    gates_kernel<<<ROWS / THREADS, THREADS>>>(x, W_ih, b_ih, b_hh);
    lstm_kernel<<<Bb, THREADS>>>(W_hh);
    fc_kernel<<<ROWS / THREADS, THREADS>>>(W_fc, b_fc, out);
}

// round 5
// speedup vs baseline: 1.1572x; 1.1572x over previous
#include <cuda_runtime.h>

// ImprovedRNN (LSTM) B=256, T=1024, I=64, H=25, O=64, fp32.
// Gate order (PyTorch): i, f, g, o = rows 0..24, 25..49, 50..74, 75..99.
//
// Phase 1 (gates_kernel): gates_x = x @ W_ih^T + (b_ih+b_hh), written as
//   g_gates[(b*T+t)*25 + j] = float4{ i_j, f_j, g_j, o_j }   (interleaved!)
//   using packed fma.rn.f32x2 (FFMA2) to halve FMA instruction count.
// Phase 2 (lstm_fc_kernel): one WARP per batch element, barrier-free
//   recurrence via __shfl_sync; FC output fused into the same shuffle loop.

static constexpr int Bb = 256;
static constexpr int Tt = 1024;
static constexpr int Ii = 64;
static constexpr int Hh = 25;
static constexpr int Gg = 4 * Hh;   // 100
static constexpr int Oo = 64;
static constexpr int ROWS = Bb * Tt;

typedef unsigned long long ull;

// Scratch (device global: allocation APIs are forbidden). ~100 MB.
__device__ float g_gates[(size_t)ROWS * Gg];

// ---- packed f32x2 helpers (sm_100+ only; ptxas never auto-fuses these) ----
__device__ __forceinline__ ull ffma2(ull a, ull b, ull c) {
    ull d;
    asm("fma.rn.f32x2 %0, %1, %2, %3;" : "=l"(d) : "l"(a), "l"(b), "l"(c));
    return d;
}
__device__ __forceinline__ ull pack2(float lo, float hi) {
    ull r;
    asm("mov.b64 %0, {%1, %2};" : "=l"(r) : "f"(lo), "f"(hi));
    return r;
}
__device__ __forceinline__ float2 unpack2(ull v) {
    float2 r;
    asm("mov.b64 {%0, %1}, %2;" : "=f"(r.x), "=f"(r.y) : "l"(v));
    return r;
}

__device__ __forceinline__ float sigmoid_f(float x) {
    return __fdividef(1.0f, 1.0f + __expf(-x));
}
__device__ __forceinline__ float tanh_f(float x) {
    return 2.0f * __fdividef(1.0f, 1.0f + __expf(-2.0f * x)) - 1.0f;
}

// ---------------------------------------------------------------------------
// Phase 1: one thread per (b,t) row. x row packed {xi,xi} in registers,
// W_ih pre-paired (i,f)/(g,o) in shared. 3200 FFMA2 per row.
// ---------------------------------------------------------------------------
__global__ __launch_bounds__(128) void gates_kernel(
    const float* __restrict__ x,
    const float* __restrict__ W_ih,
    const float* __restrict__ b_ih,
    const float* __restrict__ b_hh)
{
    __shared__ ull Wif2[Hh * Ii];    // {W_ih[j][i], W_ih[25+j][i]}
    __shared__ ull Wgo2[Hh * Ii];    // {W_ih[50+j][i], W_ih[75+j][i]}
    __shared__ float4 bsh[Hh];       // {bi, bf, bg, bo} per j

    const int tid = threadIdx.x;
    for (int idx = tid; idx < Hh * Ii; idx += 128) {
        const int j = idx >> 6, i = idx & 63;
        Wif2[idx] = pack2(W_ih[j * Ii + i],        W_ih[(25 + j) * Ii + i]);
        Wgo2[idx] = pack2(W_ih[(50 + j) * Ii + i], W_ih[(75 + j) * Ii + i]);
    }
    if (tid < Hh)
        bsh[tid] = make_float4(b_ih[tid]      + b_hh[tid],
                               b_ih[25 + tid] + b_hh[25 + tid],
                               b_ih[50 + tid] + b_hh[50 + tid],
                               b_ih[75 + tid] + b_hh[75 + tid]);
    __syncthreads();

    const size_t row = (size_t)blockIdx.x * 128 + tid;

    // x row duplicated into {xi,xi} pairs (64 u64 regs).
    ull xx[Ii];
    const float4* xp = (const float4*)(x + row * Ii);
#pragma unroll
    for (int i4 = 0; i4 < Ii / 4; ++i4) {
        const float4 v = xp[i4];
        xx[4 * i4 + 0] = pack2(v.x, v.x);
        xx[4 * i4 + 1] = pack2(v.y, v.y);
        xx[4 * i4 + 2] = pack2(v.z, v.z);
        xx[4 * i4 + 3] = pack2(v.w, v.w);
    }

    float4* gout = (float4*)(g_gates + row * Gg);

#pragma unroll 1
    for (int j = 0; j < Hh; ++j) {
        ull aif0 = 0ull, aif1 = 0ull, ago0 = 0ull, ago1 = 0ull;
        const ull* wi = &Wif2[j * Ii];
        const ull* wg = &Wgo2[j * Ii];
#pragma unroll
        for (int i = 0; i < Ii; i += 2) {
            aif0 = ffma2(wi[i],     xx[i],     aif0);
            aif1 = ffma2(wi[i + 1], xx[i + 1], aif1);
            ago0 = ffma2(wg[i],     xx[i],     ago0);
            ago1 = ffma2(wg[i + 1], xx[i + 1], ago1);
        }
        const float2 fi0 = unpack2(aif0), fi1 = unpack2(aif1);
        const float2 fg0 = unpack2(ago0), fg1 = unpack2(ago1);
        const float4 b = bsh[j];
        gout[j] = make_float4(fi0.x + fi1.x + b.x,
                              fi0.y + fi1.y + b.y,
                              fg0.x + fg1.x + b.z,
                              fg0.y + fg1.y + b.w);
    }
}

// ---------------------------------------------------------------------------
// Phase 2: one warp per batch element. Lane j (<25) owns hidden unit j:
// computes gates i_j,f_j,g_j,o_j (packed FFMA2 over shuffled h), the c/h
// update is lane-local. All 32 lanes also accumulate FC rows {2j, 2j+1}
// for the PREVIOUS timestep using the same shuffled h values.
// No shared memory, no barriers.
// ---------------------------------------------------------------------------
__global__ __launch_bounds__(32) void lstm_fc_kernel(
    const float* __restrict__ W_hh,
    const float* __restrict__ W_fc,
    const float* __restrict__ b_fc,
    float* __restrict__ out)
{
    const int j = threadIdx.x;
    const int b = blockIdx.x;

    // Recurrent weights, packed (i,f) and (g,o) per k. Lanes >=25 get zeros.
    ull wif[Hh], wgo[Hh], wfc[Hh];
#pragma unroll
    for (int k = 0; k < Hh; ++k) { wif[k] = 0ull; wgo[k] = 0ull; }
    if (j < Hh) {
#pragma unroll
        for (int k = 0; k < Hh; ++k) {
            wif[k] = pack2(W_hh[j * Hh + k],        W_hh[(25 + j) * Hh + k]);
            wgo[k] = pack2(W_hh[(50 + j) * Hh + k], W_hh[(75 + j) * Hh + k]);
        }
    }
    // FC weights: lane j owns output rows 2j, 2j+1 (all 32 lanes valid).
#pragma unroll
    for (int k = 0; k < Hh; ++k)
        wfc[k] = pack2(W_fc[(2 * j) * Hh + k], W_fc[(2 * j + 1) * Hh + k]);
    const ull bfc2 = pack2(b_fc[2 * j], b_fc[2 * j + 1]);

    const float4* gp = (const float4*)g_gates + (size_t)b * Tt * Hh + j;
    float* op = out + (size_t)b * Tt * Oo + 2 * j;

    float h = 0.0f, cst = 0.0f;
    float4 gin0 = (j < Hh) ? gp[0]      : make_float4(0, 0, 0, 0);
    float4 gin1 = (j < Hh) ? gp[Hh]     : make_float4(0, 0, 0, 0);

#pragma unroll 1
    for (int t = 0; t < Tt; ++t) {
        // Prefetch gates for t+2 (covers L2/DRAM latency, ~2 step times).
        float4 ginN = make_float4(0, 0, 0, 0);
        if (t + 2 < Tt && j < Hh) ginN = gp[(size_t)(t + 2) * Hh];

        ull aif0 = 0ull, aif1 = 0ull, ago0 = 0ull, ago1 = 0ull;
        ull afc0 = bfc2, afc1 = 0ull;
#pragma unroll
        for (int k = 0; k < Hh; ++k) {
            const float hk = __shfl_sync(0xffffffffu, h, k);
            const ull h2 = pack2(hk, hk);
            if (k & 1) {
                aif1 = ffma2(wif[k], h2, aif1);
                ago1 = ffma2(wgo[k], h2, ago1);
                afc1 = ffma2(wfc[k], h2, afc1);
            } else {
                aif0 = ffma2(wif[k], h2, aif0);
                ago0 = ffma2(wgo[k], h2, ago0);
                afc0 = ffma2(wfc[k], h2, afc0);
            }
        }

        // FC output for row t-1 (h currently holds h_{t-1}).
        if (t > 0) {
            const float2 f0 = unpack2(afc0), f1 = unpack2(afc1);
            *(float2*)(op + (size_t)(t - 1) * Oo) =
                make_float2(f0.x + f1.x, f0.y + f1.y);
        }

        const float2 gif0 = unpack2(aif0), gif1 = unpack2(aif1);
        const float2 ggo0 = unpack2(ago0), ggo1 = unpack2(ago1);
        const float gi = gin0.x + gif0.x + gif1.x;
        const float gf = gin0.y + gif0.y + gif1.y;
        const float gg = gin0.z + ggo0.x + ggo1.x;
        const float go = gin0.w + ggo0.y + ggo1.y;

        const float iv = sigmoid_f(gi);
        const float fv = sigmoid_f(gf);
        const float gv = tanh_f(gg);
        const float ov = sigmoid_f(go);
        cst = fv * cst + iv * gv;
        const float hn = ov * tanh_f(cst);
        h = (j < Hh) ? hn : 0.0f;

        gin0 = gin1;
        gin1 = ginN;
    }

    // Epilogue: FC for the final hidden state (row T-1).
    {
        ull afc0 = bfc2, afc1 = 0ull;
#pragma unroll
        for (int k = 0; k < Hh; ++k) {
            const float hk = __shfl_sync(0xffffffffu, h, k);
            const ull h2 = pack2(hk, hk);
            if (k & 1) afc1 = ffma2(wfc[k], h2, afc1);
            else       afc0 = ffma2(wfc[k], h2, afc0);
        }
        const float2 f0 = unpack2(afc0), f1 = unpack2(afc1);
        *(float2*)(op + (size_t)(Tt - 1) * Oo) =
            make_float2(f0.x + f1.x, f0.y + f1.y);
    }
}

// ---------------------------------------------------------------------------
extern "C" void kernel_launch(void* const* d_in, const int* in_sizes, int n_in,
                              void* d_out, int out_size)
{
    const float* x    = (const float*)d_in[0];
    const float* W_ih = (const float*)d_in[1];
    const float* W_hh = (const float*)d_in[2];
    const float* b_ih = (const float*)d_in[3];
    const float* b_hh = (const float*)d_in[4];
    const float* W_fc = (const float*)d_in[5];
    const float* b_fc = (const float*)d_in[6];
    float* out = (float*)d_out;

    gates_kernel<<<ROWS / 128, 128>>>(x, W_ih, b_ih, b_hh);
    lstm_fc_kernel<<<Bb, 32>>>(W_hh, W_fc, b_fc, out);
}